// round 9
// baseline (speedup 1.0000x reference)
#include <cuda_runtime.h>
#include <cuda_fp16.h>
#include <cstdint>

// Problem constants (N=100000, E=1600000, IN_DIM=128, H=4, D=16)
#define MAX_N 100000
#define MAX_E 1600000
#define HD    64
#define KD    128
#define NHEAD 4

// ---------------- device scratch (static; no cudaMalloc allowed) -------------
// g_cnt relies on zero-init at load; k_scan re-zeroes it each call so every
// graph replay re-enters with g_cnt == 0.
__device__ __half g_h16[MAX_N * HD];      // projected features [N,64] fp16
__device__ float2 g_esrc2[MAX_N * NHEAD]; // per (node,head): {exp(s_src), exp(.2 s_src)}
__device__ float2 g_edst2[MAX_N * NHEAD]; // per (node,head): {exp(s_dst), exp(.2 s_dst)}
__device__ int    g_cnt[MAX_N];           // in-degree histogram (zeroed by k_scan)
__device__ int    g_off[MAX_N];           // exclusive prefix (mutated by permute)
__device__ int    g_src_sorted[MAX_E];    // src node id, binned by dst

// ---------------- helpers -----------------------------------------------------
__device__ __forceinline__ uint32_t smem_u32(const void* p) {
    uint32_t a;
    asm("{ .reg .u64 t; cvta.to.shared.u64 t, %1; cvt.u32.u64 %0, t; }"
        : "=r"(a) : "l"(p));
    return a;
}
__device__ __forceinline__ uint32_t f2h2(float a, float b) {
    __half2 h = __floats2half2_rn(a, b);         // low = a, high = b
    return *reinterpret_cast<uint32_t*>(&h);
}

// ---------------- GEMM via mma.sync + fused scores -> node exp factors -------
__global__ void __launch_bounds__(256) k_gemm(const float* __restrict__ x,
                                              const float* __restrict__ W,
                                              const float* __restrict__ a_src,
                                              const float* __restrict__ a_dst,
                                              int n) {
    extern __shared__ __half xsm[];              // [128][128] fp16, swizzled
    __shared__ float sb1[128 * NHEAD];           // score accum: h . a_src
    __shared__ float sb2[128 * NHEAD];           // score accum: h . a_dst
    const int tid  = threadIdx.x;
    const int row0 = blockIdx.x * 128;
    const int lane = tid & 31;
    const int warp = tid >> 5;
    const int g    = lane >> 2;                  // groupID
    const int ct   = lane & 3;                   // thread-in-group

#pragma unroll
    for (int i = tid; i < 512; i += 256) { sb1[i] = 0.f; sb2[i] = 0.f; }

    const uint32_t xs_base = smem_u32(xsm);
#pragma unroll
    for (int it = 0; it < 8; it++) {
        int ci  = it * 256 + tid;
        int r   = ci >> 4;
        int c   = ci & 15;
        int row = row0 + r;
        float4 v0 = make_float4(0.f, 0.f, 0.f, 0.f), v1 = v0;
        if (row < n) {
            v0 = ((const float4*)x)[row * 32 + c * 2];
            v1 = ((const float4*)x)[row * 32 + c * 2 + 1];
        }
        uint4 pk;
        pk.x = f2h2(v0.x, v0.y); pk.y = f2h2(v0.z, v0.w);
        pk.z = f2h2(v1.x, v1.y); pk.w = f2h2(v1.z, v1.w);
        int phys = c ^ (r & 7);
        *(uint4*)((char*)xsm + r * 256 + phys * 16) = pk;
    }

    uint32_t bf[8][2];
    {
        const float* wp = W + (warp * 8 + g) * KD + ct * 2;
#pragma unroll
        for (int ks = 0; ks < 8; ks++) {
            float2 lo = *(const float2*)(wp + ks * 16);
            float2 hi = *(const float2*)(wp + ks * 16 + 8);
            bf[ks][0] = f2h2(lo.x, lo.y);
            bf[ks][1] = f2h2(hi.x, hi.y);
        }
    }
    __syncthreads();

    float acc[8][4] = {};
#pragma unroll
    for (int ks = 0; ks < 8; ks++) {
#pragma unroll
        for (int mt = 0; mt < 8; mt++) {
            int r     = mt * 16 + (lane & 15);
            int chunk = ks * 2 + (lane >> 4);
            int phys  = chunk ^ (r & 7);
            uint32_t addr = xs_base + r * 256 + phys * 16;
            uint32_t a0, a1, a2, a3;
            asm volatile(
                "ldmatrix.sync.aligned.m8n8.x4.shared.b16 {%0,%1,%2,%3}, [%4];"
                : "=r"(a0), "=r"(a1), "=r"(a2), "=r"(a3) : "r"(addr));
            asm volatile(
                "mma.sync.aligned.m16n8k16.row.col.f32.f16.f16.f32 "
                "{%0,%1,%2,%3}, {%4,%5,%6,%7}, {%8,%9}, {%0,%1,%2,%3};"
                : "+f"(acc[mt][0]), "+f"(acc[mt][1]),
                  "+f"(acc[mt][2]), "+f"(acc[mt][3])
                : "r"(a0), "r"(a1), "r"(a2), "r"(a3),
                  "r"(bf[ks][0]), "r"(bf[ks][1]));
        }
    }

    const int head = warp >> 1;
    const int dofs = (warp & 1) * 8 + ct * 2;
    const float as0 = __ldg(&a_src[head * 16 + dofs]);
    const float as1 = __ldg(&a_src[head * 16 + dofs + 1]);
    const float ad0 = __ldg(&a_dst[head * 16 + dofs]);
    const float ad1 = __ldg(&a_dst[head * 16 + dofs + 1]);
    uint32_t* h2out = (uint32_t*)g_h16;
    const int colh2 = warp * 4 + ct;

#pragma unroll
    for (int mt = 0; mt < 8; mt++) {
        int rA = row0 + mt * 16 + g;
        int rB = rA + 8;
        if (rA < n) h2out[rA * 32 + colh2] = f2h2(acc[mt][0], acc[mt][1]);
        if (rB < n) h2out[rB * 32 + colh2] = f2h2(acc[mt][2], acc[mt][3]);

        float s1a = acc[mt][0] * as0 + acc[mt][1] * as1;
        float s1b = acc[mt][2] * as0 + acc[mt][3] * as1;
        float s2a = acc[mt][0] * ad0 + acc[mt][1] * ad1;
        float s2b = acc[mt][2] * ad0 + acc[mt][3] * ad1;
#pragma unroll
        for (int d = 1; d <= 2; d <<= 1) {
            s1a += __shfl_xor_sync(0xffffffffu, s1a, d);
            s1b += __shfl_xor_sync(0xffffffffu, s1b, d);
            s2a += __shfl_xor_sync(0xffffffffu, s2a, d);
            s2b += __shfl_xor_sync(0xffffffffu, s2b, d);
        }
        if (ct == 0) {
            int mA = mt * 16 + g;
            atomicAdd(&sb1[mA * NHEAD + head], s1a);
            atomicAdd(&sb1[(mA + 8) * NHEAD + head], s1b);
            atomicAdd(&sb2[mA * NHEAD + head], s2a);
            atomicAdd(&sb2[(mA + 8) * NHEAD + head], s2b);
        }
    }
    __syncthreads();
    // Per (node, head): store {exp(s), exp(0.2 s)} for src and dst roles.
    // Separable softmax: exp(leaky(sA+sB)) = (uA*uB > 1) ? uA*uB : tA*tB.
#pragma unroll
    for (int i = tid; i < 512; i += 256) {
        int node = row0 + (i >> 2);
        int hh   = i & 3;
        if (node < n) {
            float s1 = sb1[i], s2 = sb2[i];
            g_esrc2[node * NHEAD + hh] = make_float2(__expf(s1), __expf(0.2f * s1));
            g_edst2[node * NHEAD + hh] = make_float2(__expf(s2), __expf(0.2f * s2));
        }
    }
}

// ---------------- in-degree histogram (4 independent REDs per thread) --------
__global__ void k_hist(const int* __restrict__ ei, int E) {
    int t = blockIdx.x * blockDim.x + threadIdx.x;
    int i4 = t * 4;
    if (i4 >= E) return;
    if ((E & 3) == 0) {
        int4 d = *(const int4*)&ei[E + i4];
        atomicAdd(&g_cnt[d.x], 1);
        atomicAdd(&g_cnt[d.y], 1);
        atomicAdd(&g_cnt[d.z], 1);
        atomicAdd(&g_cnt[d.w], 1);
    } else {
#pragma unroll
        for (int j = 0; j < 4; j++)
            if (i4 + j < E) atomicAdd(&g_cnt[ei[E + i4 + j]], 1);
    }
}

// ---------------- fused exclusive scan: ONE block, int4 tiles ----------------
// Also zeroes g_cnt so the next graph replay starts from a clean histogram.
__global__ void __launch_bounds__(1024) k_scan(int n) {
    __shared__ int wsum[32];
    __shared__ int s_carry;
    const int t = threadIdx.x, lane = t & 31, w = t >> 5;
    int carry = 0;
    const int ntiles = (n + 4095) >> 12;
    for (int tile = 0; tile < ntiles; tile++) {
        int base = (tile << 12) + t * 4;
        int v0 = 0, v1 = 0, v2 = 0, v3 = 0;
        if (base + 3 < n) {
            int4 c = *(int4*)&g_cnt[base];
            v0 = c.x; v1 = c.y; v2 = c.z; v3 = c.w;
            *(int4*)&g_cnt[base] = make_int4(0, 0, 0, 0);
        } else {
            if (base + 0 < n) { v0 = g_cnt[base + 0]; g_cnt[base + 0] = 0; }
            if (base + 1 < n) { v1 = g_cnt[base + 1]; g_cnt[base + 1] = 0; }
            if (base + 2 < n) { v2 = g_cnt[base + 2]; g_cnt[base + 2] = 0; }
        }
        int tsum = v0 + v1 + v2 + v3;
        int inc = tsum;
#pragma unroll
        for (int d = 1; d < 32; d <<= 1) {
            int o = __shfl_up_sync(0xffffffffu, inc, d);
            if (lane >= d) inc += o;
        }
        if (lane == 31) wsum[w] = inc;
        __syncthreads();
        if (w == 0) {
            int x = wsum[lane];
            int wi = x;
#pragma unroll
            for (int d = 1; d < 32; d <<= 1) {
                int o = __shfl_up_sync(0xffffffffu, wi, d);
                if (lane >= d) wi += o;
            }
            wsum[lane] = wi - x;            // exclusive prefix of warp totals
        }
        __syncthreads();
        int excl = carry + wsum[w] + (inc - tsum);
        if (base + 3 < n) {
            *(int4*)&g_off[base] =
                make_int4(excl, excl + v0, excl + v0 + v1, excl + v0 + v1 + v2);
        } else {
            int e = excl;
            if (base + 0 < n) { g_off[base + 0] = e; e += v0; }
            if (base + 1 < n) { g_off[base + 1] = e; e += v1; }
            if (base + 2 < n) { g_off[base + 2] = e; }
        }
        if (t == 1023) s_carry = excl + tsum;
        __syncthreads();
        carry = s_carry;
    }
}

// ---------------- permute: pure integer binning (no float traffic) -----------
// After this pass, g_off[i] == end offset of node i (start = g_off[i-1]).
__global__ void k_permute(const int* __restrict__ ei, int E) {
    int t = blockIdx.x * blockDim.x + threadIdx.x;
    int i4 = t * 4;
    if (i4 >= E) return;
    if ((E & 3) == 0) {
        int4 sv = *(const int4*)&ei[i4];
        int4 dv = *(const int4*)&ei[E + i4];
        g_src_sorted[atomicAdd(&g_off[dv.x], 1)] = sv.x;
        g_src_sorted[atomicAdd(&g_off[dv.y], 1)] = sv.y;
        g_src_sorted[atomicAdd(&g_off[dv.z], 1)] = sv.z;
        g_src_sorted[atomicAdd(&g_off[dv.w], 1)] = sv.w;
    } else {
#pragma unroll
        for (int j = 0; j < 4; j++)
            if (i4 + j < E)
                g_src_sorted[atomicAdd(&g_off[ei[E + i4 + j]], 1)] = ei[i4 + j];
    }
}

// ---------------- pull accumulate: chunked index prefetch + shfl broadcast ---
// Warp per node. Per 32-edge chunk: one coalesced LDG loads the chunk's src
// ids into lane registers; the per-edge src then comes from __shfl (register),
// so every gather in the unrolled inner loop is independent -> all fly at once.
// 32 lanes = 4 edge-slots x 8 lanes; each lane gathers 16B of h per edge.
__global__ void k_accum(float* __restrict__ out, int n) {
    int warp = (blockIdx.x * blockDim.x + threadIdx.x) >> 5;
    if (warp >= n) return;
    int lane = threadIdx.x & 31;
    int slot = lane >> 3;          // edge slot 0..3
    int sub  = lane & 7;           // 8 halfs per lane: cols sub*8..sub*8+7
    int head = sub >> 1;           // col/16
    int start = warp ? g_off[warp - 1] : 0;   // g_off holds end offsets now
    int end   = g_off[warp];

    const float2 vw = __ldg(&g_edst2[warp * NHEAD + head]);  // dst factors

    float a0 = 0.f, a1 = 0.f, a2 = 0.f, a3 = 0.f;
    float a4 = 0.f, a5 = 0.f, a6 = 0.f, a7 = 0.f;
    float sume = 0.f;
    const uint4* h16 = (const uint4*)g_h16;

    for (int cbase = start; cbase < end; cbase += 32) {
        int li = cbase + lane;
        int src_l = (li < end) ? __ldg(&g_src_sorted[li]) : 0;
        int rem = end - cbase;                 // edges in this chunk (may >32 clipped by j<32)
#pragma unroll
        for (int i = 0; i < 8; i++) {
            int j = slot + 4 * i;              // 0..31, lane-static
            int srcj = __shfl_sync(0xffffffffu, src_l, j);
            if (j < rem) {
                float2 ut  = __ldg(&g_esrc2[srcj * NHEAD + head]);
                uint4  raw = __ldg(&h16[srcj * 8 + sub]);
                float  p   = ut.x * vw.x;
                float expe = (p > 1.f) ? p : ut.y * vw.y;
                float2 f0  = __half22float2(*(const __half2*)&raw.x);
                float2 f1  = __half22float2(*(const __half2*)&raw.y);
                float2 f2  = __half22float2(*(const __half2*)&raw.z);
                float2 f3  = __half22float2(*(const __half2*)&raw.w);
                a0 = fmaf(f0.x, expe, a0); a1 = fmaf(f0.y, expe, a1);
                a2 = fmaf(f1.x, expe, a2); a3 = fmaf(f1.y, expe, a3);
                a4 = fmaf(f2.x, expe, a4); a5 = fmaf(f2.y, expe, a5);
                a6 = fmaf(f3.x, expe, a6); a7 = fmaf(f3.y, expe, a7);
                sume += expe;
            }
        }
    }
#pragma unroll
    for (int d = 8; d <= 16; d <<= 1) {
        a0 += __shfl_xor_sync(0xffffffffu, a0, d);
        a1 += __shfl_xor_sync(0xffffffffu, a1, d);
        a2 += __shfl_xor_sync(0xffffffffu, a2, d);
        a3 += __shfl_xor_sync(0xffffffffu, a3, d);
        a4 += __shfl_xor_sync(0xffffffffu, a4, d);
        a5 += __shfl_xor_sync(0xffffffffu, a5, d);
        a6 += __shfl_xor_sync(0xffffffffu, a6, d);
        a7 += __shfl_xor_sync(0xffffffffu, a7, d);
        sume += __shfl_xor_sync(0xffffffffu, sume, d);
    }
    if (slot == 0) {
        float r = 1.f / fmaxf(sume, 1e-9f);
        float4* o4 = (float4*)out + warp * 16 + sub * 2;
        o4[0] = make_float4(a0 * r, a1 * r, a2 * r, a3 * r);
        o4[1] = make_float4(a4 * r, a5 * r, a6 * r, a7 * r);
    }
}

// ---------------- launch: s2 = hist->scan->permute (int only) || gemm --------
extern "C" void kernel_launch(void* const* d_in, const int* in_sizes, int n_in,
                              void* d_out, int out_size) {
    const float* x     = (const float*)d_in[0];
    const float* W     = (const float*)d_in[1];
    const float* a_src = (const float*)d_in[2];
    const float* a_dst = (const float*)d_in[3];
    const int*   ei    = (const int*)d_in[4];
    float*       out   = (float*)d_out;

    const int n = in_sizes[0] / KD;
    const int E = in_sizes[4] / 2;

    static cudaStream_t s2 = nullptr;
    static cudaEvent_t evFork = nullptr, evJoin = nullptr;
    if (!s2) {
        cudaStreamCreateWithFlags(&s2, cudaStreamNonBlocking);
        cudaEventCreateWithFlags(&evFork, cudaEventDisableTiming);
        cudaEventCreateWithFlags(&evJoin, cudaEventDisableTiming);
    }

    // Fork: full binning chain on s2 (no dependence on GEMM).
    cudaEventRecord(evFork, 0);
    cudaStreamWaitEvent(s2, evFork, 0);

    k_hist   <<<((E + 3) / 4 + 255) / 256, 256, 0, s2>>>(ei, E);
    k_scan   <<<1, 1024, 0, s2>>>(n);
    k_permute<<<((E + 3) / 4 + 255) / 256, 256, 0, s2>>>(ei, E);
    cudaEventRecord(evJoin, s2);

    k_gemm <<<(n + 127) / 128, 256, 128 * 128 * 2>>>(x, W, a_src, a_dst, n);

    // Join: accum needs h + exp factors (main) and sorted edges (s2).
    cudaStreamWaitEvent(0, evJoin, 0);
    k_accum<<<(n * 32 + 255) / 256, 256>>>(out, n);
}

// round 11
// speedup vs baseline: 1.0053x; 1.0053x over previous
#include <cuda_runtime.h>
#include <cuda_fp16.h>
#include <cstdint>

// Problem constants (N=100000, E=1600000, IN_DIM=128, H=4, D=16)
#define MAX_N 100000
#define MAX_E 1600000
#define HD    64
#define KD    128
#define NHEAD 4

// ---------------- device scratch (static; no cudaMalloc allowed) -------------
// g_cnt relies on zero-init at load; k_scan re-zeroes it each call so every
// graph replay re-enters with g_cnt == 0.
__device__ __half g_h16[MAX_N * HD];      // projected features [N,64] fp16
__device__ float2 g_esrc2[MAX_N * NHEAD]; // per (node,head): {exp(s_src), exp(.2 s_src)}
__device__ float2 g_edst2[MAX_N * NHEAD]; // per (node,head): {exp(s_dst), exp(.2 s_dst)}
__device__ int    g_cnt[MAX_N];           // in-degree histogram (zeroed by k_scan)
__device__ int    g_off[MAX_N];           // exclusive prefix (mutated by permute)
__device__ int    g_src_sorted[MAX_E];    // src node id, binned by dst

// ---------------- helpers -----------------------------------------------------
__device__ __forceinline__ uint32_t smem_u32(const void* p) {
    uint32_t a;
    asm("{ .reg .u64 t; cvta.to.shared.u64 t, %1; cvt.u32.u64 %0, t; }"
        : "=r"(a) : "l"(p));
    return a;
}
__device__ __forceinline__ uint32_t f2h2(float a, float b) {
    __half2 h = __floats2half2_rn(a, b);         // low = a, high = b
    return *reinterpret_cast<uint32_t*>(&h);
}

// ---------------- GEMM via mma.sync: 64-row tiles, batched loads -------------
// Block: 256 threads (8 warps). Tile: 64 rows x 64 cols x K=128.
// Warp w owns output cols [w*8, w*8+8). Smaller tile -> fewer regs -> higher
// occupancy; load phase batches all LDGs before converts for MLP.
__global__ void __launch_bounds__(256) k_gemm(const float* __restrict__ x,
                                              const float* __restrict__ W,
                                              const float* __restrict__ a_src,
                                              const float* __restrict__ a_dst,
                                              int n) {
    extern __shared__ __half xsm[];              // [64][128] fp16, swizzled (16KB)
    __shared__ float sb1[64 * NHEAD];            // score accum: h . a_src
    __shared__ float sb2[64 * NHEAD];            // score accum: h . a_dst
    const int tid  = threadIdx.x;
    const int row0 = blockIdx.x * 64;
    const int lane = tid & 31;
    const int warp = tid >> 5;
    const int g    = lane >> 2;                  // groupID
    const int ct   = lane & 3;                   // thread-in-group

    if (tid < 256) { sb1[tid] = 0.f; sb2[tid] = 0.f; }

    // ---- load x tile (64x128 fp32): batch all 8 LDG.128 first, then convert --
    const uint32_t xs_base = smem_u32(xsm);
    float4 va[4], vb[4];
#pragma unroll
    for (int it = 0; it < 4; it++) {
        int ci  = it * 256 + tid;
        int r   = ci >> 4;                       // row in tile (0..63)
        int c   = ci & 15;                       // 16B chunk in row
        int row = row0 + r;
        va[it] = make_float4(0.f, 0.f, 0.f, 0.f);
        vb[it] = va[it];
        if (row < n) {
            va[it] = ((const float4*)x)[row * 32 + c * 2];
            vb[it] = ((const float4*)x)[row * 32 + c * 2 + 1];
        }
    }
#pragma unroll
    for (int it = 0; it < 4; it++) {
        int ci = it * 256 + tid;
        int r  = ci >> 4;
        int c  = ci & 15;
        uint4 pk;
        pk.x = f2h2(va[it].x, va[it].y); pk.y = f2h2(va[it].z, va[it].w);
        pk.z = f2h2(vb[it].x, vb[it].y); pk.w = f2h2(vb[it].z, vb[it].w);
        int phys = c ^ (r & 7);
        *(uint4*)((char*)xsm + r * 256 + phys * 16) = pk;
    }

    // ---- B fragments: W rows [warp*8, warp*8+8), all 8 k-steps, in regs ----
    uint32_t bf[8][2];
    {
        const float* wp = W + (warp * 8 + g) * KD + ct * 2;
#pragma unroll
        for (int ks = 0; ks < 8; ks++) {
            float2 lo = *(const float2*)(wp + ks * 16);
            float2 hi = *(const float2*)(wp + ks * 16 + 8);
            bf[ks][0] = f2h2(lo.x, lo.y);
            bf[ks][1] = f2h2(hi.x, hi.y);
        }
    }
    __syncthreads();

    // ---- main loop: 8 k-steps x 4 m-tiles of m16n8k16 ----
    float acc[4][4] = {};
#pragma unroll
    for (int ks = 0; ks < 8; ks++) {
#pragma unroll
        for (int mt = 0; mt < 4; mt++) {
            int r     = mt * 16 + (lane & 15);
            int chunk = ks * 2 + (lane >> 4);
            int phys  = chunk ^ (r & 7);
            uint32_t addr = xs_base + r * 256 + phys * 16;
            uint32_t a0, a1, a2, a3;
            asm volatile(
                "ldmatrix.sync.aligned.m8n8.x4.shared.b16 {%0,%1,%2,%3}, [%4];"
                : "=r"(a0), "=r"(a1), "=r"(a2), "=r"(a3) : "r"(addr));
            asm volatile(
                "mma.sync.aligned.m16n8k16.row.col.f32.f16.f16.f32 "
                "{%0,%1,%2,%3}, {%4,%5,%6,%7}, {%8,%9}, {%0,%1,%2,%3};"
                : "+f"(acc[mt][0]), "+f"(acc[mt][1]),
                  "+f"(acc[mt][2]), "+f"(acc[mt][3])
                : "r"(a0), "r"(a1), "r"(a2), "r"(a3),
                  "r"(bf[ks][0]), "r"(bf[ks][1]));
        }
    }

    // ---- epilogue: write h (fp16) + fused attention scores ----
    const int head = warp >> 1;                  // cols [head*16, head*16+16)
    const int dofs = (warp & 1) * 8 + ct * 2;    // d within head
    const float as0 = __ldg(&a_src[head * 16 + dofs]);
    const float as1 = __ldg(&a_src[head * 16 + dofs + 1]);
    const float ad0 = __ldg(&a_dst[head * 16 + dofs]);
    const float ad1 = __ldg(&a_dst[head * 16 + dofs + 1]);
    uint32_t* h2out = (uint32_t*)g_h16;          // half2 units
    const int colh2 = warp * 4 + ct;

#pragma unroll
    for (int mt = 0; mt < 4; mt++) {
        int rA = row0 + mt * 16 + g;
        int rB = rA + 8;
        if (rA < n) h2out[rA * 32 + colh2] = f2h2(acc[mt][0], acc[mt][1]);
        if (rB < n) h2out[rB * 32 + colh2] = f2h2(acc[mt][2], acc[mt][3]);

        float s1a = acc[mt][0] * as0 + acc[mt][1] * as1;
        float s1b = acc[mt][2] * as0 + acc[mt][3] * as1;
        float s2a = acc[mt][0] * ad0 + acc[mt][1] * ad1;
        float s2b = acc[mt][2] * ad0 + acc[mt][3] * ad1;
#pragma unroll
        for (int d = 1; d <= 2; d <<= 1) {
            s1a += __shfl_xor_sync(0xffffffffu, s1a, d);
            s1b += __shfl_xor_sync(0xffffffffu, s1b, d);
            s2a += __shfl_xor_sync(0xffffffffu, s2a, d);
            s2b += __shfl_xor_sync(0xffffffffu, s2b, d);
        }
        if (ct == 0) {
            int mA = mt * 16 + g;
            atomicAdd(&sb1[mA * NHEAD + head], s1a);
            atomicAdd(&sb1[(mA + 8) * NHEAD + head], s1b);
            atomicAdd(&sb2[mA * NHEAD + head], s2a);
            atomicAdd(&sb2[(mA + 8) * NHEAD + head], s2b);
        }
    }
    __syncthreads();
    // Per (node, head): store {exp(s), exp(0.2 s)} for src and dst roles.
    // Separable softmax: exp(leaky(sA+sB)) = (uA*uB > 1) ? uA*uB : tA*tB.
    if (tid < 256) {
        int node = row0 + (tid >> 2);
        int hh   = tid & 3;
        if (node < n) {
            float s1 = sb1[tid], s2 = sb2[tid];
            g_esrc2[node * NHEAD + hh] = make_float2(__expf(s1), __expf(0.2f * s1));
            g_edst2[node * NHEAD + hh] = make_float2(__expf(s2), __expf(0.2f * s2));
        }
    }
}

// ---------------- in-degree histogram (4 independent REDs per thread) --------
__global__ void k_hist(const int* __restrict__ ei, int E) {
    int t = blockIdx.x * blockDim.x + threadIdx.x;
    int i4 = t * 4;
    if (i4 >= E) return;
    if ((E & 3) == 0) {
        int4 d = *(const int4*)&ei[E + i4];
        atomicAdd(&g_cnt[d.x], 1);
        atomicAdd(&g_cnt[d.y], 1);
        atomicAdd(&g_cnt[d.z], 1);
        atomicAdd(&g_cnt[d.w], 1);
    } else {
#pragma unroll
        for (int j = 0; j < 4; j++)
            if (i4 + j < E) atomicAdd(&g_cnt[ei[E + i4 + j]], 1);
    }
}

// ---------------- fused exclusive scan: ONE block, int4 tiles ----------------
// Also zeroes g_cnt so the next graph replay starts from a clean histogram.
__global__ void __launch_bounds__(1024) k_scan(int n) {
    __shared__ int wsum[32];
    __shared__ int s_carry;
    const int t = threadIdx.x, lane = t & 31, w = t >> 5;
    int carry = 0;
    const int ntiles = (n + 4095) >> 12;
    for (int tile = 0; tile < ntiles; tile++) {
        int base = (tile << 12) + t * 4;
        int v0 = 0, v1 = 0, v2 = 0, v3 = 0;
        if (base + 3 < n) {
            int4 c = *(int4*)&g_cnt[base];
            v0 = c.x; v1 = c.y; v2 = c.z; v3 = c.w;
            *(int4*)&g_cnt[base] = make_int4(0, 0, 0, 0);
        } else {
            if (base + 0 < n) { v0 = g_cnt[base + 0]; g_cnt[base + 0] = 0; }
            if (base + 1 < n) { v1 = g_cnt[base + 1]; g_cnt[base + 1] = 0; }
            if (base + 2 < n) { v2 = g_cnt[base + 2]; g_cnt[base + 2] = 0; }
        }
        int tsum = v0 + v1 + v2 + v3;
        int inc = tsum;
#pragma unroll
        for (int d = 1; d < 32; d <<= 1) {
            int o = __shfl_up_sync(0xffffffffu, inc, d);
            if (lane >= d) inc += o;
        }
        if (lane == 31) wsum[w] = inc;
        __syncthreads();
        if (w == 0) {
            int x = wsum[lane];
            int wi = x;
#pragma unroll
            for (int d = 1; d < 32; d <<= 1) {
                int o = __shfl_up_sync(0xffffffffu, wi, d);
                if (lane >= d) wi += o;
            }
            wsum[lane] = wi - x;            // exclusive prefix of warp totals
        }
        __syncthreads();
        int excl = carry + wsum[w] + (inc - tsum);
        if (base + 3 < n) {
            *(int4*)&g_off[base] =
                make_int4(excl, excl + v0, excl + v0 + v1, excl + v0 + v1 + v2);
        } else {
            int e = excl;
            if (base + 0 < n) { g_off[base + 0] = e; e += v0; }
            if (base + 1 < n) { g_off[base + 1] = e; e += v1; }
            if (base + 2 < n) { g_off[base + 2] = e; }
        }
        if (t == 1023) s_carry = excl + tsum;
        __syncthreads();
        carry = s_carry;
    }
}

// ---------------- permute: pure integer binning (no float traffic) -----------
// After this pass, g_off[i] == end offset of node i (start = g_off[i-1]).
__global__ void k_permute(const int* __restrict__ ei, int E) {
    int t = blockIdx.x * blockDim.x + threadIdx.x;
    int i4 = t * 4;
    if (i4 >= E) return;
    if ((E & 3) == 0) {
        int4 sv = *(const int4*)&ei[i4];
        int4 dv = *(const int4*)&ei[E + i4];
        g_src_sorted[atomicAdd(&g_off[dv.x], 1)] = sv.x;
        g_src_sorted[atomicAdd(&g_off[dv.y], 1)] = sv.y;
        g_src_sorted[atomicAdd(&g_off[dv.z], 1)] = sv.z;
        g_src_sorted[atomicAdd(&g_off[dv.w], 1)] = sv.w;
    } else {
#pragma unroll
        for (int j = 0; j < 4; j++)
            if (i4 + j < E)
                g_src_sorted[atomicAdd(&g_off[ei[E + i4 + j]], 1)] = ei[i4 + j];
    }
}

// ---------------- pull accumulate: chunked index prefetch + shfl broadcast ---
__global__ void k_accum(float* __restrict__ out, int n) {
    int warp = (blockIdx.x * blockDim.x + threadIdx.x) >> 5;
    if (warp >= n) return;
    int lane = threadIdx.x & 31;
    int slot = lane >> 3;          // edge slot 0..3
    int sub  = lane & 7;           // 8 halfs per lane: cols sub*8..sub*8+7
    int head = sub >> 1;           // col/16
    int start = warp ? g_off[warp - 1] : 0;   // g_off holds end offsets now
    int end   = g_off[warp];

    const float2 vw = __ldg(&g_edst2[warp * NHEAD + head]);  // dst factors

    float a0 = 0.f, a1 = 0.f, a2 = 0.f, a3 = 0.f;
    float a4 = 0.f, a5 = 0.f, a6 = 0.f, a7 = 0.f;
    float sume = 0.f;
    const uint4* h16 = (const uint4*)g_h16;

    for (int cbase = start; cbase < end; cbase += 32) {
        int li = cbase + lane;
        int src_l = (li < end) ? __ldg(&g_src_sorted[li]) : 0;
        int rem = end - cbase;
#pragma unroll
        for (int i = 0; i < 8; i++) {
            int j = slot + 4 * i;              // 0..31, lane-static
            int srcj = __shfl_sync(0xffffffffu, src_l, j);
            if (j < rem) {
                float2 ut  = __ldg(&g_esrc2[srcj * NHEAD + head]);
                uint4  raw = __ldg(&h16[srcj * 8 + sub]);
                float  p   = ut.x * vw.x;
                float expe = (p > 1.f) ? p : ut.y * vw.y;
                float2 f0  = __half22float2(*(const __half2*)&raw.x);
                float2 f1  = __half22float2(*(const __half2*)&raw.y);
                float2 f2  = __half22float2(*(const __half2*)&raw.z);
                float2 f3  = __half22float2(*(const __half2*)&raw.w);
                a0 = fmaf(f0.x, expe, a0); a1 = fmaf(f0.y, expe, a1);
                a2 = fmaf(f1.x, expe, a2); a3 = fmaf(f1.y, expe, a3);
                a4 = fmaf(f2.x, expe, a4); a5 = fmaf(f2.y, expe, a5);
                a6 = fmaf(f3.x, expe, a6); a7 = fmaf(f3.y, expe, a7);
                sume += expe;
            }
        }
    }
#pragma unroll
    for (int d = 8; d <= 16; d <<= 1) {
        a0 += __shfl_xor_sync(0xffffffffu, a0, d);
        a1 += __shfl_xor_sync(0xffffffffu, a1, d);
        a2 += __shfl_xor_sync(0xffffffffu, a2, d);
        a3 += __shfl_xor_sync(0xffffffffu, a3, d);
        a4 += __shfl_xor_sync(0xffffffffu, a4, d);
        a5 += __shfl_xor_sync(0xffffffffu, a5, d);
        a6 += __shfl_xor_sync(0xffffffffu, a6, d);
        a7 += __shfl_xor_sync(0xffffffffu, a7, d);
        sume += __shfl_xor_sync(0xffffffffu, sume, d);
    }
    if (slot == 0) {
        float r = 1.f / fmaxf(sume, 1e-9f);
        float4* o4 = (float4*)out + warp * 16 + sub * 2;
        o4[0] = make_float4(a0 * r, a1 * r, a2 * r, a3 * r);
        o4[1] = make_float4(a4 * r, a5 * r, a6 * r, a7 * r);
    }
}

// ---------------- launch: s2 = hist->scan->permute (int only) || gemm --------
extern "C" void kernel_launch(void* const* d_in, const int* in_sizes, int n_in,
                              void* d_out, int out_size) {
    const float* x     = (const float*)d_in[0];
    const float* W     = (const float*)d_in[1];
    const float* a_src = (const float*)d_in[2];
    const float* a_dst = (const float*)d_in[3];
    const int*   ei    = (const int*)d_in[4];
    float*       out   = (float*)d_out;

    const int n = in_sizes[0] / KD;
    const int E = in_sizes[4] / 2;

    static cudaStream_t s2 = nullptr;
    static cudaEvent_t evFork = nullptr, evJoin = nullptr;
    if (!s2) {
        cudaStreamCreateWithFlags(&s2, cudaStreamNonBlocking);
        cudaEventCreateWithFlags(&evFork, cudaEventDisableTiming);
        cudaEventCreateWithFlags(&evJoin, cudaEventDisableTiming);
    }

    // Fork: full binning chain on s2 (no dependence on GEMM).
    cudaEventRecord(evFork, 0);
    cudaStreamWaitEvent(s2, evFork, 0);

    k_hist   <<<((E + 3) / 4 + 255) / 256, 256, 0, s2>>>(ei, E);
    k_scan   <<<1, 1024, 0, s2>>>(n);
    k_permute<<<((E + 3) / 4 + 255) / 256, 256, 0, s2>>>(ei, E);
    cudaEventRecord(evJoin, s2);

    k_gemm <<<(n + 63) / 64, 256, 64 * 128 * 2>>>(x, W, a_src, a_dst, n);

    // Join: accum needs h + exp factors (main) and sorted edges (s2).
    cudaStreamWaitEvent(0, evJoin, 0);
    k_accum<<<(n * 32 + 255) / 256, 256>>>(out, n);
}